// round 4
// baseline (speedup 1.0000x reference)
#include <cuda_runtime.h>
#include <math.h>

// Problem constants
#define B_  16
#define CIN 512
#define L_  1024
#define COUT 1024
#define K_  5
#define DW  512
#define HW  196

// Output layout (concatenated tuple): out, word_embed, img_conv, attn
#define OUT_MAIN 0
#define OUT_WE   8388608u          // 16*512*1024
#define OUT_IMG  16777216u         // + 16*1024*512
#define OUT_ATTN 18382848u         // + 16*512*196
// total 21594112

// Scratch (device globals; allocation-free rule)
__device__ float g_w[COUT * CIN * K_];        // normalized conv weights
__device__ float g_h[B_ * DW * L_];           // GLU output (B, 512, L)
__device__ float g_q[B_ * L_ * DW];           // q (B, L, 512)
__device__ float g_ctx[B_ * L_ * DW];         // ctx (B, L, 512)

// ---------------------------------------------------------------------------
// Kernel 1: weight norm.  w[co] = g[co]/||v[co]|| * v[co]
// ---------------------------------------------------------------------------
__global__ void wnorm_kernel(const float* __restrict__ v,
                             const float* __restrict__ g) {
    int co = blockIdx.x;
    const float* vr = v + (size_t)co * (CIN * K_);
    float s = 0.f;
    for (int i = threadIdx.x; i < CIN * K_; i += 256) {
        float t = vr[i];
        s += t * t;
    }
    __shared__ float red[256];
    red[threadIdx.x] = s;
    __syncthreads();
    for (int st = 128; st > 0; st >>= 1) {
        if (threadIdx.x < st) red[threadIdx.x] += red[threadIdx.x + st];
        __syncthreads();
    }
    float scale = g[co] / sqrtf(red[0]);
    float* wr = g_w + (size_t)co * (CIN * K_);
    for (int i = threadIdx.x; i < CIN * K_; i += 256) wr[i] = scale * vr[i];
}

// ---------------------------------------------------------------------------
// Kernel 2: causal conv (left pad 4) + GLU -> g_h (B, 512, L)
//   y[b,co,l] = sum_{c,t} x[b,c,l-4+t] * w[co,c,t] + bias[co]
//   h[b,ch,l] = y[b,ch,l] * sigmoid(y[b,ch+512,l])     ch in [0,512)
// Block tile: 32 h-channels x 64 l positions, one batch. 128 threads.
// Thread: 4 channels x 4 l positions (for both a- and b-half) = 32 accums.
// ---------------------------------------------------------------------------
__global__ __launch_bounds__(128) void conv_glu_kernel(
    const float* __restrict__ x, const float* __restrict__ bias) {
    __shared__ float xs[8 * 68];       // 8 cin x (64+4) window, xs[col]=x[l0+col-4]
    __shared__ float wAs[40 * 32];     // [cc*5+t][ch]  a-half weights
    __shared__ float wBs[40 * 32];     // b-half weights

    const int b   = blockIdx.z;
    const int l0  = blockIdx.x * 64;
    const int ca0 = blockIdx.y * 32;
    const int tid = threadIdx.x;
    const int tx = tid & 15;           // l group
    const int ty = tid >> 4;           // 0..7, channel group of 4

    float accA[4][4] = {};
    float accB[4][4] = {};
    const float* xb = x + (size_t)b * CIN * L_;

    for (int c0 = 0; c0 < CIN; c0 += 8) {
        // stage x window
        for (int idx = tid; idx < 8 * 68; idx += 128) {
            int cc = idx / 68, col = idx % 68;
            int gl = l0 + col - 4;
            xs[idx] = (gl >= 0) ? xb[(size_t)(c0 + cc) * L_ + gl] : 0.f;
        }
        // stage weights transposed: [r=cc*5+t][ch]
        for (int idx = tid; idx < 1280; idx += 128) {
            int ch = idx / 40, r = idx % 40;
            int cc = r / 5, t = r - cc * 5;
            wAs[r * 32 + ch] = g_w[(size_t)(ca0 + ch) * (CIN * K_) + (c0 + cc) * K_ + t];
            wBs[r * 32 + ch] = g_w[(size_t)(ca0 + ch + 512) * (CIN * K_) + (c0 + cc) * K_ + t];
        }
        __syncthreads();

#pragma unroll
        for (int cc = 0; cc < 8; cc++) {
#pragma unroll
            for (int t = 0; t < K_; t++) {
                const int r = cc * K_ + t;
                float4 wa4 = *(const float4*)&wAs[r * 32 + ty * 4];
                float4 wb4 = *(const float4*)&wBs[r * 32 + ty * 4];
                float wav[4] = {wa4.x, wa4.y, wa4.z, wa4.w};
                float wbv[4] = {wb4.x, wb4.y, wb4.z, wb4.w};
                float xv[4];
#pragma unroll
                for (int j = 0; j < 4; j++) xv[j] = xs[cc * 68 + tx * 4 + t + j];
#pragma unroll
                for (int i = 0; i < 4; i++)
#pragma unroll
                    for (int j = 0; j < 4; j++) {
                        accA[i][j] = fmaf(wav[i], xv[j], accA[i][j]);
                        accB[i][j] = fmaf(wbv[i], xv[j], accB[i][j]);
                    }
            }
        }
        __syncthreads();
    }

    // epilogue: GLU, write h
#pragma unroll
    for (int i = 0; i < 4; i++) {
        int ca = ca0 + ty * 4 + i;
        float ba = bias[ca];
        float bb = bias[ca + 512];
        float4 hv;
        float ya, yb;
        ya = accA[i][0] + ba; yb = accB[i][0] + bb; hv.x = ya / (1.f + expf(-yb));
        ya = accA[i][1] + ba; yb = accB[i][1] + bb; hv.y = ya / (1.f + expf(-yb));
        ya = accA[i][2] + ba; yb = accB[i][2] + bb; hv.z = ya / (1.f + expf(-yb));
        ya = accA[i][3] + ba; yb = accB[i][3] + bb; hv.w = ya / (1.f + expf(-yb));
        *(float4*)&g_h[((size_t)b * 512 + ca) * L_ + l0 + tx * 4] = hv;
    }
}

// ---------------------------------------------------------------------------
// Kernel 3: fc1.  q[b,l,a] = sum_c h[b,c,l]*w1[a,c] + b1[a] + we[b,l,a]
// 64l x 64a tile, 256 threads, 4x4 per thread, K chunks of 16.
// ---------------------------------------------------------------------------
__global__ __launch_bounds__(256) void fc1_kernel(
    const float* __restrict__ w1, const float* __restrict__ b1,
    const float* __restrict__ we) {
    __shared__ float hs[16 * 68];   // [cc][l]
    __shared__ float ws[16 * 68];   // [cc][a]
    const int b = blockIdx.z, l0 = blockIdx.x * 64, a0 = blockIdx.y * 64;
    const int tid = threadIdx.x;
    const int tx = tid & 15, ty = tid >> 4;
    float acc[4][4] = {};  // [li][aj]
    const float* hb = g_h + (size_t)b * 512 * L_;

    for (int c0 = 0; c0 < 512; c0 += 16) {
        for (int idx = tid; idx < 1024; idx += 256) {
            int cc = idx >> 6, ll = idx & 63;
            hs[cc * 68 + ll] = hb[(size_t)(c0 + cc) * L_ + l0 + ll];
        }
        for (int idx = tid; idx < 1024; idx += 256) {
            int aL = idx >> 4, cc = idx & 15;
            ws[cc * 68 + aL] = w1[(size_t)(a0 + aL) * 512 + c0 + cc];
        }
        __syncthreads();
#pragma unroll
        for (int cc = 0; cc < 16; cc++) {
            float4 h4 = *(const float4*)&hs[cc * 68 + tx * 4];
            float4 w4 = *(const float4*)&ws[cc * 68 + ty * 4];
            float hv[4] = {h4.x, h4.y, h4.z, h4.w};
            float wv[4] = {w4.x, w4.y, w4.z, w4.w};
#pragma unroll
            for (int li = 0; li < 4; li++)
#pragma unroll
                for (int aj = 0; aj < 4; aj++)
                    acc[li][aj] = fmaf(hv[li], wv[aj], acc[li][aj]);
        }
        __syncthreads();
    }
    float4 bb4 = *(const float4*)&b1[a0 + ty * 4];
    float bb[4] = {bb4.x, bb4.y, bb4.z, bb4.w};
#pragma unroll
    for (int li = 0; li < 4; li++) {
        int l = l0 + tx * 4 + li;
        size_t off = ((size_t)b * L_ + l) * 512 + a0 + ty * 4;
        float4 wev = *(const float4*)&we[off];
        float4 o;
        o.x = acc[li][0] + bb[0] + wev.x;
        o.y = acc[li][1] + bb[1] + wev.y;
        o.z = acc[li][2] + bb[2] + wev.z;
        o.w = acc[li][3] + bb[3] + wev.w;
        *(float4*)&g_q[off] = o;
    }
}

// ---------------------------------------------------------------------------
// Kernel 4: attention. Per (b, 32-l tile):
//   score[l,p] = sum_a q[b,l,a]*feat[b,a,p] ; attn = softmax_p ; write attn out
//   ctx[b,l,a] = sum_p attn[l,p]*feat[b,a,p]
// Dynamic smem: ss[32][197] + fsT[196][33] + qs[32][33]
// ---------------------------------------------------------------------------
#define ATTN_SMEM_FLOATS (32 * 197 + 196 * 33 + 32 * 33)
__global__ __launch_bounds__(256) void attn_kernel(
    const float* __restrict__ feat, float* __restrict__ attn_out) {
    extern __shared__ float sm[];
    float* ss  = sm;                    // [32][197] score -> attn
    float* fsT = sm + 32 * 197;         // [196][33] feat chunk transposed [p][a]
    float* qs  = sm + 32 * 197 + 196 * 33;  // [32][33]

    const int b = blockIdx.y, l0 = blockIdx.x * 32;
    const int tid = threadIdx.x;
    const float* qb = g_q + ((size_t)b * L_ + l0) * 512;
    const float* fb = feat + (size_t)b * 512 * HW;

    // ---- phase 1: score ----
    float acc[32];
#pragma unroll
    for (int i = 0; i < 32; i++) acc[i] = 0.f;

    for (int a0 = 0; a0 < 512; a0 += 32) {
        for (int idx = tid; idx < 1024; idx += 256) {
            int l = idx >> 5, a = idx & 31;
            qs[l * 33 + a] = qb[(size_t)l * 512 + a0 + a];
        }
        for (int idx = tid; idx < 32 * HW; idx += 256) {
            int a = idx / HW, p = idx - a * HW;
            fsT[p * 33 + a] = fb[(size_t)(a0 + a) * HW + p];
        }
        __syncthreads();
        if (tid < HW) {
#pragma unroll 4
            for (int aa = 0; aa < 32; aa++) {
                float fv = fsT[tid * 33 + aa];
#pragma unroll
                for (int l = 0; l < 32; l++)
                    acc[l] = fmaf(qs[l * 33 + aa], fv, acc[l]);
            }
        }
        __syncthreads();
    }
    if (tid < HW) {
#pragma unroll
        for (int l = 0; l < 32; l++) ss[l * 197 + tid] = acc[l];
    }
    __syncthreads();

    // ---- phase 2: softmax over p (rows of 196), 8 warps x 4 rows ----
    const int warp = tid >> 5, lane = tid & 31;
    for (int r = 0; r < 4; r++) {
        int l = warp * 4 + r;
        float v[7];
        float mx = -1e30f;
#pragma unroll
        for (int k = 0; k < 7; k++) {
            int p = lane + 32 * k;
            v[k] = (p < HW) ? ss[l * 197 + p] : -1e30f;
            mx = fmaxf(mx, v[k]);
        }
#pragma unroll
        for (int off = 16; off > 0; off >>= 1)
            mx = fmaxf(mx, __shfl_xor_sync(0xffffffffu, mx, off));
        float s = 0.f;
#pragma unroll
        for (int k = 0; k < 7; k++) {
            int p = lane + 32 * k;
            if (p < HW) { v[k] = expf(v[k] - mx); s += v[k]; }
        }
#pragma unroll
        for (int off = 16; off > 0; off >>= 1)
            s += __shfl_xor_sync(0xffffffffu, s, off);
        float inv = 1.f / s;
        float* ao = attn_out + ((size_t)b * L_ + l0 + l) * HW;
#pragma unroll
        for (int k = 0; k < 7; k++) {
            int p = lane + 32 * k;
            if (p < HW) {
                float a = v[k] * inv;
                ss[l * 197 + p] = a;
                ao[p] = a;
            }
        }
    }
    __syncthreads();

    // ---- phase 3: ctx = attn @ feat^T ----
    const int tx = tid & 7;    // a sub-group of 4
    const int ty = tid >> 3;   // l (0..31)
    float* ctxb = g_ctx + ((size_t)b * L_ + l0) * 512;
    for (int a0 = 0; a0 < 512; a0 += 32) {
        for (int idx = tid; idx < 32 * HW; idx += 256) {
            int a = idx / HW, p = idx - a * HW;
            fsT[p * 33 + a] = fb[(size_t)(a0 + a) * HW + p];
        }
        __syncthreads();
        float c4[4] = {0.f, 0.f, 0.f, 0.f};
        for (int p = 0; p < HW; p++) {
            float av = ss[ty * 197 + p];
            const float* fr = &fsT[p * 33 + tx * 4];
            c4[0] = fmaf(av, fr[0], c4[0]);
            c4[1] = fmaf(av, fr[1], c4[1]);
            c4[2] = fmaf(av, fr[2], c4[2]);
            c4[3] = fmaf(av, fr[3], c4[3]);
        }
        float4 o; o.x = c4[0]; o.y = c4[1]; o.z = c4[2]; o.w = c4[3];
        *(float4*)&ctxb[(size_t)ty * 512 + a0 + tx * 4] = o;
        __syncthreads();
    }
}

// ---------------------------------------------------------------------------
// Kernel 5: fc2 + residuals.
//   out[b,c,l] = sum_a ctx[b,l,a]*w2[c,a] + b2[c] + h[b,c,l] + x[b,c,l]
// ---------------------------------------------------------------------------
__global__ __launch_bounds__(256) void fc2_kernel(
    const float* __restrict__ w2, const float* __restrict__ b2,
    const float* __restrict__ x, float* __restrict__ out) {
    __shared__ float cs[16 * 68];   // [aa][l]
    __shared__ float ws[16 * 68];   // [aa][c]
    const int b = blockIdx.z, l0 = blockIdx.x * 64, c0 = blockIdx.y * 64;
    const int tid = threadIdx.x;
    const int tx = tid & 15, ty = tid >> 4;
    float acc[4][4] = {};  // [ci][li]

    for (int a0 = 0; a0 < 512; a0 += 16) {
        for (int idx = tid; idx < 1024; idx += 256) {
            int lL = idx >> 4, aa = idx & 15;
            cs[aa * 68 + lL] = g_ctx[((size_t)b * L_ + l0 + lL) * 512 + a0 + aa];
        }
        for (int idx = tid; idx < 1024; idx += 256) {
            int cL = idx >> 4, aa = idx & 15;
            ws[aa * 68 + cL] = w2[(size_t)(c0 + cL) * 512 + a0 + aa];
        }
        __syncthreads();
#pragma unroll
        for (int aa = 0; aa < 16; aa++) {
            float4 ct4 = *(const float4*)&cs[aa * 68 + tx * 4];
            float4 w4  = *(const float4*)&ws[aa * 68 + ty * 4];
            float cv[4] = {ct4.x, ct4.y, ct4.z, ct4.w};
            float wv[4] = {w4.x, w4.y, w4.z, w4.w};
#pragma unroll
            for (int ci = 0; ci < 4; ci++)
#pragma unroll
                for (int li = 0; li < 4; li++)
                    acc[ci][li] = fmaf(wv[ci], cv[li], acc[ci][li]);
        }
        __syncthreads();
    }
#pragma unroll
    for (int ci = 0; ci < 4; ci++) {
        int c = c0 + ty * 4 + ci;
        float bb = b2[c];
        size_t off = ((size_t)b * 512 + c) * L_ + l0 + tx * 4;
        float4 h4 = *(const float4*)&g_h[off];
        float4 x4 = *(const float4*)&x[off];
        float4 o;
        o.x = acc[ci][0] + bb + h4.x + x4.x;
        o.y = acc[ci][1] + bb + h4.y + x4.y;
        o.z = acc[ci][2] + bb + h4.z + x4.z;
        o.w = acc[ci][3] + bb + h4.w + x4.w;
        *(float4*)&out[off] = o;
    }
}

// ---------------------------------------------------------------------------
extern "C" void kernel_launch(void* const* d_in, const int* in_sizes, int n_in,
                              void* d_out, int out_size) {
    (void)in_sizes; (void)n_in; (void)out_size;
    const float* x      = (const float*)d_in[0];
    const float* we     = (const float*)d_in[1];
    const float* img    = (const float*)d_in[2];
    /* d_in[3] prev_attn unused */
    const float* conv_v = (const float*)d_in[4];
    const float* conv_g = (const float*)d_in[5];
    const float* conv_b = (const float*)d_in[6];
    const float* fc1_w  = (const float*)d_in[7];
    const float* fc1_b  = (const float*)d_in[8];
    const float* fc2_w  = (const float*)d_in[9];
    const float* fc2_b  = (const float*)d_in[10];
    float* out = (float*)d_out;

    // passthrough copies
    cudaMemcpyAsync(out + OUT_WE, we, (size_t)B_ * L_ * DW * sizeof(float),
                    cudaMemcpyDeviceToDevice, 0);
    cudaMemcpyAsync(out + OUT_IMG, img, (size_t)B_ * DW * HW * sizeof(float),
                    cudaMemcpyDeviceToDevice, 0);

    wnorm_kernel<<<COUT, 256>>>(conv_v, conv_g);
    conv_glu_kernel<<<dim3(L_ / 64, 512 / 32, B_), 128>>>(x, conv_b);
    fc1_kernel<<<dim3(L_ / 64, 512 / 64, B_), 256>>>(fc1_w, fc1_b, we);

    cudaFuncSetAttribute(attn_kernel, cudaFuncAttributeMaxDynamicSharedMemorySize,
                         ATTN_SMEM_FLOATS * (int)sizeof(float));
    attn_kernel<<<dim3(L_ / 32, B_), 256, ATTN_SMEM_FLOATS * sizeof(float)>>>(
        img, out + OUT_ATTN);

    fc2_kernel<<<dim3(L_ / 64, 512 / 64, B_), 256>>>(fc2_w, fc2_b, x, out);
}

// round 5
// speedup vs baseline: 1.0559x; 1.0559x over previous
#include <cuda_runtime.h>
#include <math.h>

// Problem constants
#define B_  16
#define CIN 512
#define L_  1024
#define COUT 1024
#define K_  5
#define DW  512
#define HW  196

// Output layout (concatenated tuple): out, word_embed, img_conv, attn
#define OUT_MAIN 0
#define OUT_WE   8388608u          // 16*512*1024
#define OUT_IMG  16777216u         // + 16*1024*512
#define OUT_ATTN 18382848u         // + 16*512*196
// total 21594112

// Scratch (device globals; allocation-free rule)
__device__ float g_w[COUT * CIN * K_];        // normalized conv weights
__device__ float g_h[B_ * DW * L_];           // GLU output (B, 512, L)
__device__ float g_q[B_ * L_ * DW];           // q (B, L, 512)
__device__ float g_ctx[B_ * L_ * DW];         // ctx (B, L, 512)

// ---------------------------------------------------------------------------
// Kernel 1: weight norm.  w[co] = g[co]/||v[co]|| * v[co]
// ---------------------------------------------------------------------------
__global__ void wnorm_kernel(const float* __restrict__ v,
                             const float* __restrict__ g) {
    int co = blockIdx.x;
    const float* vr = v + (size_t)co * (CIN * K_);
    float s = 0.f;
    for (int i = threadIdx.x; i < CIN * K_; i += 256) {
        float t = vr[i];
        s += t * t;
    }
    __shared__ float red[256];
    red[threadIdx.x] = s;
    __syncthreads();
    for (int st = 128; st > 0; st >>= 1) {
        if (threadIdx.x < st) red[threadIdx.x] += red[threadIdx.x + st];
        __syncthreads();
    }
    float scale = g[co] / sqrtf(red[0]);
    float* wr = g_w + (size_t)co * (CIN * K_);
    for (int i = threadIdx.x; i < CIN * K_; i += 256) wr[i] = scale * vr[i];
}

// ---------------------------------------------------------------------------
// Kernel 2: causal conv (left pad 4) + GLU -> g_h (B, 512, L)
//   y[b,co,l] = sum_{c,t} x[b,c,l-4+t] * w[co,c,t] + bias[co]
//   h[b,ch,l] = y[b,ch,l] * sigmoid(y[b,ch+512,l])     ch in [0,512)
// Block tile: 32 h-channels x 64 l positions, one batch. 128 threads.
// Thread: 4 channels x 4 l positions (for both a- and b-half) = 32 accums.
// ---------------------------------------------------------------------------
__global__ __launch_bounds__(128) void conv_glu_kernel(
    const float* __restrict__ x, const float* __restrict__ bias) {
    __shared__ float xs[8 * 68];       // 8 cin x (64+4) window, xs[col]=x[l0+col-4]
    __shared__ float wAs[40 * 32];     // [cc*5+t][ch]  a-half weights
    __shared__ float wBs[40 * 32];     // b-half weights

    const int b   = blockIdx.z;
    const int l0  = blockIdx.x * 64;
    const int ca0 = blockIdx.y * 32;
    const int tid = threadIdx.x;
    const int tx = tid & 15;           // l group
    const int ty = tid >> 4;           // 0..7, channel group of 4

    float accA[4][4] = {};
    float accB[4][4] = {};
    const float* xb = x + (size_t)b * CIN * L_;

    for (int c0 = 0; c0 < CIN; c0 += 8) {
        // stage x window
        for (int idx = tid; idx < 8 * 68; idx += 128) {
            int cc = idx / 68, col = idx % 68;
            int gl = l0 + col - 4;
            xs[idx] = (gl >= 0) ? xb[(size_t)(c0 + cc) * L_ + gl] : 0.f;
        }
        // stage weights transposed: [r=cc*5+t][ch]
        for (int idx = tid; idx < 1280; idx += 128) {
            int ch = idx / 40, r = idx % 40;
            int cc = r / 5, t = r - cc * 5;
            wAs[r * 32 + ch] = g_w[(size_t)(ca0 + ch) * (CIN * K_) + (c0 + cc) * K_ + t];
            wBs[r * 32 + ch] = g_w[(size_t)(ca0 + ch + 512) * (CIN * K_) + (c0 + cc) * K_ + t];
        }
        __syncthreads();

#pragma unroll
        for (int cc = 0; cc < 8; cc++) {
#pragma unroll
            for (int t = 0; t < K_; t++) {
                const int r = cc * K_ + t;
                float4 wa4 = *(const float4*)&wAs[r * 32 + ty * 4];
                float4 wb4 = *(const float4*)&wBs[r * 32 + ty * 4];
                float wav[4] = {wa4.x, wa4.y, wa4.z, wa4.w};
                float wbv[4] = {wb4.x, wb4.y, wb4.z, wb4.w};
                float xv[4];
#pragma unroll
                for (int j = 0; j < 4; j++) xv[j] = xs[cc * 68 + tx * 4 + t + j];
#pragma unroll
                for (int i = 0; i < 4; i++)
#pragma unroll
                    for (int j = 0; j < 4; j++) {
                        accA[i][j] = fmaf(wav[i], xv[j], accA[i][j]);
                        accB[i][j] = fmaf(wbv[i], xv[j], accB[i][j]);
                    }
            }
        }
        __syncthreads();
    }

    // epilogue: GLU, write h
#pragma unroll
    for (int i = 0; i < 4; i++) {
        int ca = ca0 + ty * 4 + i;
        float ba = bias[ca];
        float bb = bias[ca + 512];
        float4 hv;
        float ya, yb;
        ya = accA[i][0] + ba; yb = accB[i][0] + bb; hv.x = ya / (1.f + expf(-yb));
        ya = accA[i][1] + ba; yb = accB[i][1] + bb; hv.y = ya / (1.f + expf(-yb));
        ya = accA[i][2] + ba; yb = accB[i][2] + bb; hv.z = ya / (1.f + expf(-yb));
        ya = accA[i][3] + ba; yb = accB[i][3] + bb; hv.w = ya / (1.f + expf(-yb));
        *(float4*)&g_h[((size_t)b * 512 + ca) * L_ + l0 + tx * 4] = hv;
    }
}

// ---------------------------------------------------------------------------
// Kernel 3: fc1.  q[b,l,a] = sum_c h[b,c,l]*w1[a,c] + b1[a] + we[b,l,a]
// 64l x 64a tile, 256 threads, 4x4 per thread, K chunks of 16.
// ---------------------------------------------------------------------------
__global__ __launch_bounds__(256) void fc1_kernel(
    const float* __restrict__ w1, const float* __restrict__ b1,
    const float* __restrict__ we) {
    __shared__ float hs[16 * 68];   // [cc][l]
    __shared__ float ws[16 * 68];   // [cc][a]
    const int b = blockIdx.z, l0 = blockIdx.x * 64, a0 = blockIdx.y * 64;
    const int tid = threadIdx.x;
    const int tx = tid & 15, ty = tid >> 4;
    float acc[4][4] = {};  // [li][aj]
    const float* hb = g_h + (size_t)b * 512 * L_;

    for (int c0 = 0; c0 < 512; c0 += 16) {
        for (int idx = tid; idx < 1024; idx += 256) {
            int cc = idx >> 6, ll = idx & 63;
            hs[cc * 68 + ll] = hb[(size_t)(c0 + cc) * L_ + l0 + ll];
        }
        for (int idx = tid; idx < 1024; idx += 256) {
            int aL = idx >> 4, cc = idx & 15;
            ws[cc * 68 + aL] = w1[(size_t)(a0 + aL) * 512 + c0 + cc];
        }
        __syncthreads();
#pragma unroll
        for (int cc = 0; cc < 16; cc++) {
            float4 h4 = *(const float4*)&hs[cc * 68 + tx * 4];
            float4 w4 = *(const float4*)&ws[cc * 68 + ty * 4];
            float hv[4] = {h4.x, h4.y, h4.z, h4.w};
            float wv[4] = {w4.x, w4.y, w4.z, w4.w};
#pragma unroll
            for (int li = 0; li < 4; li++)
#pragma unroll
                for (int aj = 0; aj < 4; aj++)
                    acc[li][aj] = fmaf(hv[li], wv[aj], acc[li][aj]);
        }
        __syncthreads();
    }
    float4 bb4 = *(const float4*)&b1[a0 + ty * 4];
    float bb[4] = {bb4.x, bb4.y, bb4.z, bb4.w};
#pragma unroll
    for (int li = 0; li < 4; li++) {
        int l = l0 + tx * 4 + li;
        size_t off = ((size_t)b * L_ + l) * 512 + a0 + ty * 4;
        float4 wev = *(const float4*)&we[off];
        float4 o;
        o.x = acc[li][0] + bb[0] + wev.x;
        o.y = acc[li][1] + bb[1] + wev.y;
        o.z = acc[li][2] + bb[2] + wev.z;
        o.w = acc[li][3] + bb[3] + wev.w;
        *(float4*)&g_q[off] = o;
    }
}

// ---------------------------------------------------------------------------
// Kernel 4: attention. Per (b, 32-l tile):
//   score[l,p] = sum_a q[b,l,a]*feat[b,a,p] ; attn = softmax_p ; write attn out
//   ctx[b,l,a] = sum_p attn[l,p]*feat[b,a,p]
// Dynamic smem: ss[32][197] + fsT[196][33] + qs[32][33]
// ---------------------------------------------------------------------------
#define ATTN_SMEM_FLOATS (32 * 197 + 196 * 33 + 32 * 33)
__global__ __launch_bounds__(256) void attn_kernel(
    const float* __restrict__ feat, float* __restrict__ attn_out) {
    extern __shared__ float sm[];
    float* ss  = sm;                    // [32][197] score -> attn
    float* fsT = sm + 32 * 197;         // [196][33] feat chunk transposed [p][a]
    float* qs  = sm + 32 * 197 + 196 * 33;  // [32][33]

    const int b = blockIdx.y, l0 = blockIdx.x * 32;
    const int tid = threadIdx.x;
    const float* qb = g_q + ((size_t)b * L_ + l0) * 512;
    const float* fb = feat + (size_t)b * 512 * HW;

    // ---- phase 1: score ----
    float acc[32];
#pragma unroll
    for (int i = 0; i < 32; i++) acc[i] = 0.f;

    for (int a0 = 0; a0 < 512; a0 += 32) {
        for (int idx = tid; idx < 1024; idx += 256) {
            int l = idx >> 5, a = idx & 31;
            qs[l * 33 + a] = qb[(size_t)l * 512 + a0 + a];
        }
        for (int idx = tid; idx < 32 * HW; idx += 256) {
            int a = idx / HW, p = idx - a * HW;
            fsT[p * 33 + a] = fb[(size_t)(a0 + a) * HW + p];
        }
        __syncthreads();
        if (tid < HW) {
#pragma unroll 4
            for (int aa = 0; aa < 32; aa++) {
                float fv = fsT[tid * 33 + aa];
#pragma unroll
                for (int l = 0; l < 32; l++)
                    acc[l] = fmaf(qs[l * 33 + aa], fv, acc[l]);
            }
        }
        __syncthreads();
    }
    if (tid < HW) {
#pragma unroll
        for (int l = 0; l < 32; l++) ss[l * 197 + tid] = acc[l];
    }
    __syncthreads();

    // ---- phase 2: softmax over p (rows of 196), 8 warps x 4 rows ----
    const int warp = tid >> 5, lane = tid & 31;
    for (int r = 0; r < 4; r++) {
        int l = warp * 4 + r;
        float v[7];
        float mx = -1e30f;
#pragma unroll
        for (int k = 0; k < 7; k++) {
            int p = lane + 32 * k;
            v[k] = (p < HW) ? ss[l * 197 + p] : -1e30f;
            mx = fmaxf(mx, v[k]);
        }
#pragma unroll
        for (int off = 16; off > 0; off >>= 1)
            mx = fmaxf(mx, __shfl_xor_sync(0xffffffffu, mx, off));
        float s = 0.f;
#pragma unroll
        for (int k = 0; k < 7; k++) {
            int p = lane + 32 * k;
            if (p < HW) { v[k] = expf(v[k] - mx); s += v[k]; }
        }
#pragma unroll
        for (int off = 16; off > 0; off >>= 1)
            s += __shfl_xor_sync(0xffffffffu, s, off);
        float inv = 1.f / s;
        float* ao = attn_out + ((size_t)b * L_ + l0 + l) * HW;
#pragma unroll
        for (int k = 0; k < 7; k++) {
            int p = lane + 32 * k;
            if (p < HW) {
                float a = v[k] * inv;
                ss[l * 197 + p] = a;
                ao[p] = a;
            }
        }
    }
    __syncthreads();

    // ---- phase 3: ctx = attn @ feat^T ----
    const int tx = tid & 7;    // a sub-group of 4
    const int ty = tid >> 3;   // l (0..31)
    float* ctxb = g_ctx + ((size_t)b * L_ + l0) * 512;
    for (int a0 = 0; a0 < 512; a0 += 32) {
        for (int idx = tid; idx < 32 * HW; idx += 256) {
            int a = idx / HW, p = idx - a * HW;
            fsT[p * 33 + a] = fb[(size_t)(a0 + a) * HW + p];
        }
        __syncthreads();
        float c4[4] = {0.f, 0.f, 0.f, 0.f};
        for (int p = 0; p < HW; p++) {
            float av = ss[ty * 197 + p];
            const float* fr = &fsT[p * 33 + tx * 4];
            c4[0] = fmaf(av, fr[0], c4[0]);
            c4[1] = fmaf(av, fr[1], c4[1]);
            c4[2] = fmaf(av, fr[2], c4[2]);
            c4[3] = fmaf(av, fr[3], c4[3]);
        }
        float4 o; o.x = c4[0]; o.y = c4[1]; o.z = c4[2]; o.w = c4[3];
        *(float4*)&ctxb[(size_t)ty * 512 + a0 + tx * 4] = o;
        __syncthreads();
    }
}

// ---------------------------------------------------------------------------
// Kernel 5: fc2 + residuals.
//   out[b,c,l] = sum_a ctx[b,l,a]*w2[c,a] + b2[c] + h[b,c,l] + x[b,c,l]
// ---------------------------------------------------------------------------
__global__ __launch_bounds__(256) void fc2_kernel(
    const float* __restrict__ w2, const float* __restrict__ b2,
    const float* __restrict__ x, float* __restrict__ out) {
    __shared__ float cs[16 * 68];   // [aa][l]
    __shared__ float ws[16 * 68];   // [aa][c]
    const int b = blockIdx.z, l0 = blockIdx.x * 64, c0 = blockIdx.y * 64;
    const int tid = threadIdx.x;
    const int tx = tid & 15, ty = tid >> 4;
    float acc[4][4] = {};  // [ci][li]

    for (int a0 = 0; a0 < 512; a0 += 16) {
        for (int idx = tid; idx < 1024; idx += 256) {
            int lL = idx >> 4, aa = idx & 15;
            cs[aa * 68 + lL] = g_ctx[((size_t)b * L_ + l0 + lL) * 512 + a0 + aa];
        }
        for (int idx = tid; idx < 1024; idx += 256) {
            int cL = idx >> 4, aa = idx & 15;
            ws[aa * 68 + cL] = w2[(size_t)(c0 + cL) * 512 + a0 + aa];
        }
        __syncthreads();
#pragma unroll
        for (int aa = 0; aa < 16; aa++) {
            float4 ct4 = *(const float4*)&cs[aa * 68 + tx * 4];
            float4 w4  = *(const float4*)&ws[aa * 68 + ty * 4];
            float cv[4] = {ct4.x, ct4.y, ct4.z, ct4.w};
            float wv[4] = {w4.x, w4.y, w4.z, w4.w};
#pragma unroll
            for (int ci = 0; ci < 4; ci++)
#pragma unroll
                for (int li = 0; li < 4; li++)
                    acc[ci][li] = fmaf(wv[ci], cv[li], acc[ci][li]);
        }
        __syncthreads();
    }
#pragma unroll
    for (int ci = 0; ci < 4; ci++) {
        int c = c0 + ty * 4 + ci;
        float bb = b2[c];
        size_t off = ((size_t)b * 512 + c) * L_ + l0 + tx * 4;
        float4 h4 = *(const float4*)&g_h[off];
        float4 x4 = *(const float4*)&x[off];
        float4 o;
        o.x = acc[ci][0] + bb + h4.x + x4.x;
        o.y = acc[ci][1] + bb + h4.y + x4.y;
        o.z = acc[ci][2] + bb + h4.z + x4.z;
        o.w = acc[ci][3] + bb + h4.w + x4.w;
        *(float4*)&out[off] = o;
    }
}

// ---------------------------------------------------------------------------
extern "C" void kernel_launch(void* const* d_in, const int* in_sizes, int n_in,
                              void* d_out, int out_size) {
    (void)in_sizes; (void)n_in; (void)out_size;
    const float* x      = (const float*)d_in[0];
    const float* we     = (const float*)d_in[1];
    const float* img    = (const float*)d_in[2];
    /* d_in[3] prev_attn unused */
    const float* conv_v = (const float*)d_in[4];
    const float* conv_g = (const float*)d_in[5];
    const float* conv_b = (const float*)d_in[6];
    const float* fc1_w  = (const float*)d_in[7];
    const float* fc1_b  = (const float*)d_in[8];
    const float* fc2_w  = (const float*)d_in[9];
    const float* fc2_b  = (const float*)d_in[10];
    float* out = (float*)d_out;

    // passthrough copies
    cudaMemcpyAsync(out + OUT_WE, we, (size_t)B_ * L_ * DW * sizeof(float),
                    cudaMemcpyDeviceToDevice, 0);
    cudaMemcpyAsync(out + OUT_IMG, img, (size_t)B_ * DW * HW * sizeof(float),
                    cudaMemcpyDeviceToDevice, 0);

    wnorm_kernel<<<COUT, 256>>>(conv_v, conv_g);
    conv_glu_kernel<<<dim3(L_ / 64, 512 / 32, B_), 128>>>(x, conv_b);
    fc1_kernel<<<dim3(L_ / 64, 512 / 64, B_), 256>>>(fc1_w, fc1_b, we);

    cudaFuncSetAttribute(attn_kernel, cudaFuncAttributeMaxDynamicSharedMemorySize,
                         ATTN_SMEM_FLOATS * (int)sizeof(float));
    attn_kernel<<<dim3(L_ / 32, B_), 256, ATTN_SMEM_FLOATS * sizeof(float)>>>(
        img, out + OUT_ATTN);

    fc2_kernel<<<dim3(L_ / 64, 512 / 64, B_), 256>>>(fc2_w, fc2_b, x, out);
}

// round 7
// speedup vs baseline: 2.2236x; 2.1059x over previous
#include <cuda_runtime.h>
#include <cuda_bf16.h>
#include <math.h>

// Problem constants
#define B_  16
#define CIN 512
#define L_  1024
#define COUT 1024
#define K_  5
#define DW  512
#define HW  196
#define KCONV (CIN * K_)   // 2560

// Output layout (concatenated tuple): out, word_embed, img_conv, attn
#define OUT_WE   8388608u          // 16*512*1024
#define OUT_IMG  16777216u         // + 16*1024*512
#define OUT_ATTN 18382848u         // + 16*512*196

typedef __nv_bfloat16 bf16;

// ---------------------------------------------------------------------------
// Scratch (device globals; allocation-free rule)
// ---------------------------------------------------------------------------
__device__ float g_w[COUT * KCONV];          // normalized conv weights (co, c, t)
__device__ float g_h[B_ * DW * L_];          // GLU output fp32 (b, ch, l)
__device__ float g_q[B_ * DW * L_];          // q fp32, layout (b, a, l)
__device__ bf16 g_xh[B_ * CIN * L_],  g_xl[B_ * CIN * L_];    // x split
__device__ bf16 g_cwh[COUT * KCONV], g_cwl[COUT * KCONV];     // conv W reordered+split
__device__ bf16 g_w1h[DW * DW], g_w1l[DW * DW];               // fc1 W split [a][c]
__device__ bf16 g_w2h[DW * DW], g_w2l[DW * DW];               // fc2 W split [c][a]
__device__ bf16 g_hh[B_ * DW * L_], g_hl[B_ * DW * L_];       // h split (b, ch, l)
__device__ bf16 g_cxh[B_ * DW * L_], g_cxl[B_ * DW * L_];     // ctx split (b, a, l)

__device__ __forceinline__ void split2(float v, bf16& h, bf16& l) {
    h = __float2bfloat16(v);
    l = __float2bfloat16(v - __bfloat162float(h));
}

// ---------------------------------------------------------------------------
// Kernel 1: weight norm.  g_w[co] = g[co]/||v[co]|| * v[co]
// ---------------------------------------------------------------------------
__global__ void wnorm_kernel(const float* __restrict__ v,
                             const float* __restrict__ g) {
    int co = blockIdx.x;
    const float* vr = v + (size_t)co * KCONV;
    float s = 0.f;
    for (int i = threadIdx.x; i < KCONV; i += 256) {
        float t = vr[i];
        s += t * t;
    }
    __shared__ float red[256];
    red[threadIdx.x] = s;
    __syncthreads();
    for (int st = 128; st > 0; st >>= 1) {
        if (threadIdx.x < st) red[threadIdx.x] += red[threadIdx.x + st];
        __syncthreads();
    }
    float scale = g[co] / sqrtf(red[0]);
    float* wr = g_w + (size_t)co * KCONV;
    for (int i = threadIdx.x; i < KCONV; i += 256) wr[i] = scale * vr[i];
}

// ---------------------------------------------------------------------------
// Kernel 1b: reorder conv weights to A[m][kk], kk = t*512 + c, split to bf16.
//   m even -> a-half channel m/2 ; m odd -> b-half channel (m-1)/2 + 512
// ---------------------------------------------------------------------------
__global__ void convw_split_kernel() {
    int m = blockIdx.x;
    int co = (m & 1) ? (512 + (m >> 1)) : (m >> 1);
    const float* wr = g_w + (size_t)co * KCONV;
    for (int kk = threadIdx.x; kk < KCONV; kk += 256) {
        int t = kk >> 9, c = kk & 511;
        float v = wr[c * K_ + t];
        bf16 hi, lo; split2(v, hi, lo);
        g_cwh[(size_t)m * KCONV + kk] = hi;
        g_cwl[(size_t)m * KCONV + kk] = lo;
    }
}

// ---------------------------------------------------------------------------
// Kernel 1c: generic fp32 -> bf16 hi/lo split
// ---------------------------------------------------------------------------
__global__ void split_kernel(const float* __restrict__ src,
                             bf16* __restrict__ dh, bf16* __restrict__ dl, int n) {
    int i = blockIdx.x * blockDim.x + threadIdx.x;
    int stride = gridDim.x * blockDim.x;
    for (; i < n; i += stride) {
        bf16 hi, lo; split2(src[i], hi, lo);
        dh[i] = hi; dl[i] = lo;
    }
}

// ---------------------------------------------------------------------------
// Unified bf16-split tensor-core GEMM.  C(M,N) = A(M,K) @ B(K,N), fp32 acc.
//   MODE 0: conv. A = g_cwh/l [1024][2560], B[kk][l] = x[b][c][l + t - 4]
//           epilogue: GLU pairs (even,odd rows) + bias -> g_h, g_hh, g_hl
//   MODE 1: fc1.  A = g_w1h/l [512][512],   B = g_hh/l (b,c,l)
//           epilogue: + fc1_b + we -> g_q (b,a,l)
//   MODE 2: fc2.  A = g_w2h/l [512][512],   B = g_cxh/l (b,a,l)
//           epilogue: + fc2_b + g_h + x -> out (b,c,l)
// Split product: Ah*Bh + Ah*Bl + Al*Bh  (Al*Bl dropped, ~2^-18 relative)
// Block: 256 thr (8 warps, 4m x 2n), tile 128m x 128n, BK=32.
// ---------------------------------------------------------------------------
#define BM 128
#define BN 128
#define BK 32
#define APAD 40   // smem row pitch (elems); conflict-free fragment LDS

__device__ __forceinline__ void mma_bf16(float* c, const unsigned* a,
                                         unsigned b0, unsigned b1) {
    asm volatile(
        "mma.sync.aligned.m16n8k16.row.col.f32.bf16.bf16.f32 "
        "{%0,%1,%2,%3}, {%4,%5,%6,%7}, {%8,%9}, {%0,%1,%2,%3};\n"
        : "+f"(c[0]), "+f"(c[1]), "+f"(c[2]), "+f"(c[3])
        : "r"(a[0]), "r"(a[1]), "r"(a[2]), "r"(a[3]), "r"(b0), "r"(b1));
}

template <int MODE>
__global__ __launch_bounds__(256, 2) void gemm_kernel(
    const float* __restrict__ bias,   // conv_b / fc1_b / fc2_b
    const float* __restrict__ e1,     // unused / we / x
    float* __restrict__ outp) {       // unused / unused / out
    const int KD = (MODE == 0) ? KCONV : 512;
    const bf16* Agh = (MODE == 0) ? g_cwh : (MODE == 1) ? g_w1h : g_w2h;
    const bf16* Agl = (MODE == 0) ? g_cwl : (MODE == 1) ? g_w1l : g_w2l;
    const bf16* Bh_base = (MODE == 0) ? g_xh : (MODE == 1) ? g_hh : g_cxh;
    const bf16* Bl_base = (MODE == 0) ? g_xl : (MODE == 1) ? g_hl : g_cxl;

    const int b  = blockIdx.z;
    const int m0 = blockIdx.y * BM;
    const int l0 = blockIdx.x * BN;
    const int tid = threadIdx.x;
    const int lane = tid & 31, warp = tid >> 5;
    const int wm = warp >> 1, wn = warp & 1;

    __shared__ __align__(16) unsigned char sraw[4 * BM * APAD * 2];  // 40960 B
    bf16* As_h = (bf16*)sraw;
    bf16* As_l = As_h + BM * APAD;
    bf16* Bs_h = As_l + BM * APAD;
    bf16* Bs_l = Bs_h + BM * APAD;
    float* Cs = (float*)sraw;        // [128][65] reused for epilogue

    const bf16* Bgh = Bh_base + (size_t)b * 512 * L_;
    const bf16* Bgl = Bl_base + (size_t)b * 512 * L_;

    float acc[2][8][4];
#pragma unroll
    for (int mt = 0; mt < 2; mt++)
#pragma unroll
        for (int nt = 0; nt < 8; nt++)
#pragma unroll
            for (int j = 0; j < 4; j++) acc[mt][nt][j] = 0.f;

    for (int k0 = 0; k0 < KD; k0 += BK) {
        // ---- A tile: BM x BK, row-major, b32 (2 bf16) per load ----
#pragma unroll
        for (int i = 0; i < 8; i++) {
            int u = i * 256 + tid;
            int row = u >> 4, kp = (u & 15) << 1;
            size_t ga = (size_t)(m0 + row) * KD + k0 + kp;
            *(unsigned*)&As_h[row * APAD + kp] = *(const unsigned*)&Agh[ga];
            *(unsigned*)&As_l[row * APAD + kp] = *(const unsigned*)&Agl[ga];
        }
        // ---- B tile: stored transposed in smem as Bs[n][k] ----
        if (MODE == 0) {
            // conv: row kk -> (t,c); x shifted by t-4, left-edge zero
#pragma unroll
            for (int i = 0; i < 16; i++) {
                int e = i * 256 + tid;
                int k = e >> 7, n = e & 127;
                int kk = k0 + k;
                int t = kk >> 9, c = kk & 511;
                int l = l0 + n + t - 4;
                bf16 vh = __float2bfloat16(0.f), vl = vh;
                if (l >= 0) {
                    size_t gb = (size_t)c * L_ + l;
                    vh = Bgh[gb]; vl = Bgl[gb];
                }
                Bs_h[n * APAD + k] = vh;
                Bs_l[n * APAD + k] = vl;
            }
        } else {
#pragma unroll
            for (int i = 0; i < 8; i++) {
                int u = i * 256 + tid;
                int k = u >> 6, np = u & 63;
                size_t gb = (size_t)(k0 + k) * L_ + l0 + (np << 1);
                __nv_bfloat162 vh = *(const __nv_bfloat162*)&Bgh[gb];
                __nv_bfloat162 vl = *(const __nv_bfloat162*)&Bgl[gb];
                Bs_h[(np * 2) * APAD + k]     = vh.x;
                Bs_h[(np * 2 + 1) * APAD + k] = vh.y;
                Bs_l[(np * 2) * APAD + k]     = vl.x;
                Bs_l[(np * 2 + 1) * APAD + k] = vl.y;
            }
        }
        __syncthreads();

#pragma unroll
        for (int ks = 0; ks < BK; ks += 16) {
            const int kb = ks + (lane & 3) * 2;
            unsigned ah[2][4], al[2][4];
#pragma unroll
            for (int mt = 0; mt < 2; mt++) {
                int rb = wm * 32 + mt * 16 + (lane >> 2);
                ah[mt][0] = *(unsigned*)&As_h[rb * APAD + kb];
                ah[mt][1] = *(unsigned*)&As_h[(rb + 8) * APAD + kb];
                ah[mt][2] = *(unsigned*)&As_h[rb * APAD + kb + 8];
                ah[mt][3] = *(unsigned*)&As_h[(rb + 8) * APAD + kb + 8];
                al[mt][0] = *(unsigned*)&As_l[rb * APAD + kb];
                al[mt][1] = *(unsigned*)&As_l[(rb + 8) * APAD + kb];
                al[mt][2] = *(unsigned*)&As_l[rb * APAD + kb + 8];
                al[mt][3] = *(unsigned*)&As_l[(rb + 8) * APAD + kb + 8];
            }
#pragma unroll
            for (int nt = 0; nt < 8; nt++) {
                int col = wn * 64 + nt * 8 + (lane >> 2);
                unsigned bh0 = *(unsigned*)&Bs_h[col * APAD + kb];
                unsigned bh1 = *(unsigned*)&Bs_h[col * APAD + kb + 8];
                unsigned bl0 = *(unsigned*)&Bs_l[col * APAD + kb];
                unsigned bl1 = *(unsigned*)&Bs_l[col * APAD + kb + 8];
#pragma unroll
                for (int mt = 0; mt < 2; mt++) {
                    mma_bf16(acc[mt][nt], ah[mt], bh0, bh1);
                    mma_bf16(acc[mt][nt], ah[mt], bl0, bl1);
                    mma_bf16(acc[mt][nt], al[mt], bh0, bh1);
                }
            }
        }
        __syncthreads();
    }

    // ---- epilogue: two 64-col passes through Cs[128][65] ----
#pragma unroll 1
    for (int p = 0; p < 2; p++) {
        if (wn == p) {
#pragma unroll
            for (int mt = 0; mt < 2; mt++)
#pragma unroll
                for (int nt = 0; nt < 8; nt++) {
                    int r = wm * 32 + mt * 16 + (lane >> 2);
                    int cl = nt * 8 + (lane & 3) * 2;
                    Cs[r * 65 + cl]           = acc[mt][nt][0];
                    Cs[r * 65 + cl + 1]       = acc[mt][nt][1];
                    Cs[(r + 8) * 65 + cl]     = acc[mt][nt][2];
                    Cs[(r + 8) * 65 + cl + 1] = acc[mt][nt][3];
                }
        }
        __syncthreads();
        const int lbase = l0 + p * 64;
        if (MODE == 0) {
            int ch0 = m0 >> 1;
#pragma unroll
            for (int i = 0; i < 16; i++) {
                int e = i * 256 + tid;
                int chl = e >> 6, ll = e & 63;
                float av = Cs[(chl * 2) * 65 + ll] + __ldg(&bias[ch0 + chl]);
                float bv = Cs[(chl * 2 + 1) * 65 + ll] + __ldg(&bias[512 + ch0 + chl]);
                float hv = av / (1.f + expf(-bv));
                size_t off = ((size_t)b * 512 + ch0 + chl) * L_ + lbase + ll;
                g_h[off] = hv;
                bf16 hi, lo; split2(hv, hi, lo);
                g_hh[off] = hi; g_hl[off] = lo;
            }
        } else if (MODE == 1) {
            // pass A (a-major, coalesced we reads): Cs += b1 + we
#pragma unroll
            for (int i = 0; i < 32; i++) {
                int e = i * 256 + tid;
                int a = e & 127, ll = e >> 7;
                Cs[a * 65 + ll] += __ldg(&bias[m0 + a]) +
                    e1[((size_t)b * L_ + lbase + ll) * 512 + m0 + a];
            }
            __syncthreads();
            // pass B (l-major, coalesced q writes)
#pragma unroll
            for (int i = 0; i < 32; i++) {
                int e = i * 256 + tid;
                int a = e >> 6, ll = e & 63;
                g_q[((size_t)b * 512 + m0 + a) * L_ + lbase + ll] = Cs[a * 65 + ll];
            }
        } else {
#pragma unroll
            for (int i = 0; i < 32; i++) {
                int e = i * 256 + tid;
                int cl_ = e >> 6, ll = e & 63;
                size_t off = ((size_t)b * 512 + m0 + cl_) * L_ + lbase + ll;
                outp[off] = Cs[cl_ * 65 + ll] + __ldg(&bias[m0 + cl_])
                          + g_h[off] + e1[off];
            }
        }
        __syncthreads();
    }
}

// ---------------------------------------------------------------------------
// Attention. q layout (b,a,l); ctx emitted split bf16 to g_cxh/g_cxl (b,a,l).
// ---------------------------------------------------------------------------
#define ATTN_SMEM_FLOATS (32 * 197 + 196 * 33 + 32 * 33)
__global__ __launch_bounds__(256) void attn_kernel(
    const float* __restrict__ feat, float* __restrict__ attn_out) {
    extern __shared__ float sm[];
    float* ss  = sm;                        // [32][197] score -> attn
    float* fsT = sm + 32 * 197;             // [196][33] feat chunk transposed [p][a]
    float* qs  = sm + 32 * 197 + 196 * 33;  // [32][33] (reused as ctx stage)

    const int b = blockIdx.y, l0 = blockIdx.x * 32;
    const int tid = threadIdx.x;
    const float* qb = g_q + (size_t)b * 512 * L_;
    const float* fb = feat + (size_t)b * 512 * HW;

    // ---- phase 1: score ----
    float acc[32];
#pragma unroll
    for (int i = 0; i < 32; i++) acc[i] = 0.f;

    for (int a0 = 0; a0 < 512; a0 += 32) {
        for (int idx = tid; idx < 1024; idx += 256) {
            int a = idx >> 5, l = idx & 31;
            qs[l * 33 + a] = qb[(size_t)(a0 + a) * L_ + l0 + l];
        }
        for (int idx = tid; idx < 32 * HW; idx += 256) {
            int a = idx / HW, p = idx - a * HW;
            fsT[p * 33 + a] = fb[(size_t)(a0 + a) * HW + p];
        }
        __syncthreads();
        if (tid < HW) {
#pragma unroll 4
            for (int aa = 0; aa < 32; aa++) {
                float fv = fsT[tid * 33 + aa];
#pragma unroll
                for (int l = 0; l < 32; l++)
                    acc[l] = fmaf(qs[l * 33 + aa], fv, acc[l]);
            }
        }
        __syncthreads();
    }
    if (tid < HW) {
#pragma unroll
        for (int l = 0; l < 32; l++) ss[l * 197 + tid] = acc[l];
    }
    __syncthreads();

    // ---- phase 2: softmax over p ----
    const int warp = tid >> 5, lane = tid & 31;
    for (int r = 0; r < 4; r++) {
        int l = warp * 4 + r;
        float v[7];
        float mx = -1e30f;
#pragma unroll
        for (int k = 0; k < 7; k++) {
            int p = lane + 32 * k;
            v[k] = (p < HW) ? ss[l * 197 + p] : -1e30f;
            mx = fmaxf(mx, v[k]);
        }
#pragma unroll
        for (int off = 16; off > 0; off >>= 1)
            mx = fmaxf(mx, __shfl_xor_sync(0xffffffffu, mx, off));
        float s = 0.f;
#pragma unroll
        for (int k = 0; k < 7; k++) {
            int p = lane + 32 * k;
            if (p < HW) { v[k] = expf(v[k] - mx); s += v[k]; }
        }
#pragma unroll
        for (int off = 16; off > 0; off >>= 1)
            s += __shfl_xor_sync(0xffffffffu, s, off);
        float inv = 1.f / s;
        float* ao = attn_out + ((size_t)b * L_ + l0 + l) * HW;
#pragma unroll
        for (int k = 0; k < 7; k++) {
            int p = lane + 32 * k;
            if (p < HW) {
                float a = v[k] * inv;
                ss[l * 197 + p] = a;
                ao[p] = a;
            }
        }
    }
    __syncthreads();

    // ---- phase 3: ctx = attn @ feat^T, emit bf16 hi/lo (b,a,l) ----
    const int tx = tid & 7;    // a sub-group of 4
    const int ty = tid >> 3;   // l (0..31)
    for (int a0 = 0; a0 < 512; a0 += 32) {
        for (int idx = tid; idx < 32 * HW; idx += 256) {
            int a = idx / HW, p = idx - a * HW;
            fsT[p * 33 + a] = fb[(size_t)(a0 + a) * HW + p];
        }
        __syncthreads();
        float c4[4] = {0.f, 0.f, 0.f, 0.f};
        for (int p = 0; p < HW; p++) {
            float av = ss[ty * 197 + p];
            const float* fr = &fsT[p * 33 + tx * 4];
            c4[0] = fmaf(av, fr[0], c4[0]);
            c4[1] = fmaf(av, fr[1], c4[1]);
            c4[2] = fmaf(av, fr[2], c4[2]);
            c4[3] = fmaf(av, fr[3], c4[3]);
        }
#pragma unroll
        for (int j = 0; j < 4; j++) qs[(tx * 4 + j) * 33 + ty] = c4[j];
        __syncthreads();
        for (int idx = tid; idx < 1024; idx += 256) {
            int a = idx >> 5, l = idx & 31;
            float v = qs[a * 33 + l];
            bf16 hi, lo; split2(v, hi, lo);
            size_t off = ((size_t)b * 512 + a0 + a) * L_ + l0 + l;
            g_cxh[off] = hi;
            g_cxl[off] = lo;
        }
        __syncthreads();
    }
}

// ---------------------------------------------------------------------------
extern "C" void kernel_launch(void* const* d_in, const int* in_sizes, int n_in,
                              void* d_out, int out_size) {
    (void)in_sizes; (void)n_in; (void)out_size;
    const float* x      = (const float*)d_in[0];
    const float* we     = (const float*)d_in[1];
    const float* img    = (const float*)d_in[2];
    /* d_in[3] prev_attn unused */
    const float* conv_v = (const float*)d_in[4];
    const float* conv_g = (const float*)d_in[5];
    const float* conv_b = (const float*)d_in[6];
    const float* fc1_w  = (const float*)d_in[7];
    const float* fc1_b  = (const float*)d_in[8];
    const float* fc2_w  = (const float*)d_in[9];
    const float* fc2_b  = (const float*)d_in[10];
    float* out = (float*)d_out;

    // passthrough copies
    cudaMemcpyAsync(out + OUT_WE, we, (size_t)B_ * L_ * DW * sizeof(float),
                    cudaMemcpyDeviceToDevice, 0);
    cudaMemcpyAsync(out + OUT_IMG, img, (size_t)B_ * DW * HW * sizeof(float),
                    cudaMemcpyDeviceToDevice, 0);

    // device-symbol addresses for split targets
    void *p_xh, *p_xl, *p_w1h, *p_w1l, *p_w2h, *p_w2l;
    cudaGetSymbolAddress(&p_xh, g_xh);
    cudaGetSymbolAddress(&p_xl, g_xl);
    cudaGetSymbolAddress(&p_w1h, g_w1h);
    cudaGetSymbolAddress(&p_w1l, g_w1l);
    cudaGetSymbolAddress(&p_w2h, g_w2h);
    cudaGetSymbolAddress(&p_w2l, g_w2l);

    // prep
    wnorm_kernel<<<COUT, 256>>>(conv_v, conv_g);
    convw_split_kernel<<<COUT, 256>>>();
    split_kernel<<<2048, 256>>>(x, (bf16*)p_xh, (bf16*)p_xl, B_ * CIN * L_);
    split_kernel<<<256, 256>>>(fc1_w, (bf16*)p_w1h, (bf16*)p_w1l, DW * DW);
    split_kernel<<<256, 256>>>(fc2_w, (bf16*)p_w2h, (bf16*)p_w2l, DW * DW);

    // conv + GLU  (M=1024 interleaved, N=1024, K=2560)
    gemm_kernel<0><<<dim3(L_ / BN, COUT / BM, B_), 256>>>(conv_b, nullptr, nullptr);
    // fc1 (M=512, N=1024, K=512)
    gemm_kernel<1><<<dim3(L_ / BN, DW / BM, B_), 256>>>(fc1_b, we, nullptr);

    // attention
    cudaFuncSetAttribute(attn_kernel, cudaFuncAttributeMaxDynamicSharedMemorySize,
                         ATTN_SMEM_FLOATS * (int)sizeof(float));
    attn_kernel<<<dim3(L_ / 32, B_), 256, ATTN_SMEM_FLOATS * sizeof(float)>>>(
        img, out + OUT_ATTN);

    // fc2 + residuals (M=512, N=1024, K=512)
    gemm_kernel<2><<<dim3(L_ / BN, DW / BM, B_), 256>>>(fc2_b, x, out);
}

// round 8
// speedup vs baseline: 2.7815x; 1.2509x over previous
#include <cuda_runtime.h>
#include <cuda_bf16.h>
#include <math.h>

// Problem constants
#define B_  16
#define CIN 512
#define L_  1024
#define COUT 1024
#define K_  5
#define DW  512
#define HW  196
#define KCONV (CIN * K_)   // 2560
#define PP  224            // padded p dimension (HW=196 -> 224)

// Output layout (concatenated tuple): out, word_embed, img_conv, attn
#define OUT_WE   8388608u          // 16*512*1024
#define OUT_IMG  16777216u         // + 16*1024*512
#define OUT_ATTN 18382848u         // + 16*512*196

typedef __nv_bfloat16 bf16;

// ---------------------------------------------------------------------------
// Scratch (device globals; allocation-free rule)
// ---------------------------------------------------------------------------
__device__ float g_w[COUT * KCONV];          // normalized conv weights (co, c, t)
__device__ float g_h[B_ * DW * L_];          // GLU output fp32 (b, ch, l)
__device__ bf16 g_xh[B_ * CIN * L_],  g_xl[B_ * CIN * L_];    // x split
__device__ bf16 g_cwh[COUT * KCONV], g_cwl[COUT * KCONV];     // conv W reordered+split
__device__ bf16 g_w1h[DW * DW], g_w1l[DW * DW];               // fc1 W split [a][c]
__device__ bf16 g_w2h[DW * DW], g_w2l[DW * DW];               // fc2 W split [c][a]
__device__ bf16 g_hh[B_ * DW * L_], g_hl[B_ * DW * L_];       // h split (b, ch, l)
__device__ bf16 g_qh[B_ * L_ * DW], g_ql[B_ * L_ * DW];       // q split (b, l, a)
__device__ bf16 g_cxh[B_ * DW * L_], g_cxl[B_ * DW * L_];     // ctx split (b, a, l)
__device__ bf16 g_fTh[B_ * PP * DW], g_fTl[B_ * PP * DW];     // feat^T split (b, p, a), p>=196 zero
__device__ bf16 g_fh[B_ * DW * PP],  g_fl[B_ * DW * PP];      // feat split (b, a, p), p>=196 zero

__device__ __forceinline__ void split2(float v, bf16& h, bf16& l) {
    h = __float2bfloat16(v);
    l = __float2bfloat16(v - __bfloat162float(h));
}

// ---------------------------------------------------------------------------
// Kernel 1: weight norm.  g_w[co] = g[co]/||v[co]|| * v[co]
// ---------------------------------------------------------------------------
__global__ void wnorm_kernel(const float* __restrict__ v,
                             const float* __restrict__ g) {
    int co = blockIdx.x;
    const float* vr = v + (size_t)co * KCONV;
    float s = 0.f;
    for (int i = threadIdx.x; i < KCONV; i += 256) {
        float t = vr[i];
        s += t * t;
    }
    __shared__ float red[256];
    red[threadIdx.x] = s;
    __syncthreads();
    for (int st = 128; st > 0; st >>= 1) {
        if (threadIdx.x < st) red[threadIdx.x] += red[threadIdx.x + st];
        __syncthreads();
    }
    float scale = g[co] / sqrtf(red[0]);
    float* wr = g_w + (size_t)co * KCONV;
    for (int i = threadIdx.x; i < KCONV; i += 256) wr[i] = scale * vr[i];
}

// ---------------------------------------------------------------------------
// Kernel 1b: reorder conv weights to A[m][kk], kk = t*512 + c, split to bf16.
// ---------------------------------------------------------------------------
__global__ void convw_split_kernel() {
    int m = blockIdx.x;
    int co = (m & 1) ? (512 + (m >> 1)) : (m >> 1);
    const float* wr = g_w + (size_t)co * KCONV;
    for (int kk = threadIdx.x; kk < KCONV; kk += 256) {
        int t = kk >> 9, c = kk & 511;
        float v = wr[c * K_ + t];
        bf16 hi, lo; split2(v, hi, lo);
        g_cwh[(size_t)m * KCONV + kk] = hi;
        g_cwl[(size_t)m * KCONV + kk] = lo;
    }
}

// ---------------------------------------------------------------------------
// Kernel 1c: generic fp32 -> bf16 hi/lo split
// ---------------------------------------------------------------------------
__global__ void split_kernel(const float* __restrict__ src,
                             bf16* __restrict__ dh, bf16* __restrict__ dl, int n) {
    int i = blockIdx.x * blockDim.x + threadIdx.x;
    int stride = gridDim.x * blockDim.x;
    for (; i < n; i += stride) {
        bf16 hi, lo; split2(src[i], hi, lo);
        dh[i] = hi; dl[i] = lo;
    }
}

// ---------------------------------------------------------------------------
// Kernel 1d: feat^T split (b, p, a) from img (b, a, p); p>=196 rows zero.
// 32x32 smem tile transpose. block (32,8), grid (PP/32, 512/32, B)
// ---------------------------------------------------------------------------
__global__ void featT_kernel(const float* __restrict__ img) {
    __shared__ float t[32][33];
    const int b = blockIdx.z, p0 = blockIdx.x * 32, a0 = blockIdx.y * 32;
    const int tx = threadIdx.x, ty0 = threadIdx.y;
#pragma unroll
    for (int j = 0; j < 4; j++) {
        int ty = ty0 + j * 8;
        int a = a0 + ty, p = p0 + tx;
        t[ty][tx] = (p < HW) ? img[((size_t)b * 512 + a) * HW + p] : 0.f;
    }
    __syncthreads();
#pragma unroll
    for (int j = 0; j < 4; j++) {
        int ty = ty0 + j * 8;
        float v = t[tx][ty];   // element (a0+tx, p0+ty)
        bf16 hi, lo; split2(v, hi, lo);
        size_t off = ((size_t)b * PP + p0 + ty) * 512 + a0 + tx;
        g_fTh[off] = hi; g_fTl[off] = lo;
    }
}

// ---------------------------------------------------------------------------
// Kernel 1e: feat split + p-pad (b, a, PP) from img (b, a, 196)
// ---------------------------------------------------------------------------
__global__ void featpad_kernel(const float* __restrict__ img) {
    int idx = blockIdx.x * 256 + threadIdx.x;
    if (idx >= B_ * 512 * PP) return;
    int p = idx % PP, ba = idx / PP;
    float v = (p < HW) ? img[(size_t)ba * HW + p] : 0.f;
    bf16 hi, lo; split2(v, hi, lo);
    g_fh[idx] = hi; g_fl[idx] = lo;
}

// ---------------------------------------------------------------------------
// Unified bf16-split tensor-core GEMM (conv / fc1 / fc2). See R7 notes.
// ---------------------------------------------------------------------------
#define BM 128
#define BN 128
#define BK 32
#define APAD 40   // smem row pitch (elems)

__device__ __forceinline__ void mma_bf16(float* c, const unsigned* a,
                                         unsigned b0, unsigned b1) {
    asm volatile(
        "mma.sync.aligned.m16n8k16.row.col.f32.bf16.bf16.f32 "
        "{%0,%1,%2,%3}, {%4,%5,%6,%7}, {%8,%9}, {%0,%1,%2,%3};\n"
        : "+f"(c[0]), "+f"(c[1]), "+f"(c[2]), "+f"(c[3])
        : "r"(a[0]), "r"(a[1]), "r"(a[2]), "r"(a[3]), "r"(b0), "r"(b1));
}

template <int MODE>
__global__ __launch_bounds__(256, 2) void gemm_kernel(
    const float* __restrict__ bias,   // conv_b / fc1_b / fc2_b
    const float* __restrict__ e1,     // unused / we / x
    float* __restrict__ outp) {       // unused / unused / out
    const int KD = (MODE == 0) ? KCONV : 512;
    const bf16* Agh = (MODE == 0) ? g_cwh : (MODE == 1) ? g_w1h : g_w2h;
    const bf16* Agl = (MODE == 0) ? g_cwl : (MODE == 1) ? g_w1l : g_w2l;
    const bf16* Bh_base = (MODE == 0) ? g_xh : (MODE == 1) ? g_hh : g_cxh;
    const bf16* Bl_base = (MODE == 0) ? g_xl : (MODE == 1) ? g_hl : g_cxl;

    const int b  = blockIdx.z;
    const int m0 = blockIdx.y * BM;
    const int l0 = blockIdx.x * BN;
    const int tid = threadIdx.x;
    const int lane = tid & 31, warp = tid >> 5;
    const int wm = warp >> 1, wn = warp & 1;

    __shared__ __align__(16) unsigned char sraw[4 * BM * APAD * 2];  // 40960 B
    bf16* As_h = (bf16*)sraw;
    bf16* As_l = As_h + BM * APAD;
    bf16* Bs_h = As_l + BM * APAD;
    bf16* Bs_l = Bs_h + BM * APAD;
    float* Cs = (float*)sraw;        // [128][65] reused for epilogue

    const bf16* Bgh = Bh_base + (size_t)b * 512 * L_;
    const bf16* Bgl = Bl_base + (size_t)b * 512 * L_;

    float acc[2][8][4];
#pragma unroll
    for (int mt = 0; mt < 2; mt++)
#pragma unroll
        for (int nt = 0; nt < 8; nt++)
#pragma unroll
            for (int j = 0; j < 4; j++) acc[mt][nt][j] = 0.f;

    for (int k0 = 0; k0 < KD; k0 += BK) {
        // ---- A tile ----
#pragma unroll
        for (int i = 0; i < 8; i++) {
            int u = i * 256 + tid;
            int row = u >> 4, kp = (u & 15) << 1;
            size_t ga = (size_t)(m0 + row) * KD + k0 + kp;
            *(unsigned*)&As_h[row * APAD + kp] = *(const unsigned*)&Agh[ga];
            *(unsigned*)&As_l[row * APAD + kp] = *(const unsigned*)&Agl[ga];
        }
        // ---- B tile (transposed in smem: Bs[n][k]) ----
        if (MODE == 0) {
#pragma unroll
            for (int i = 0; i < 16; i++) {
                int e = i * 256 + tid;
                int k = e >> 7, n = e & 127;
                int kk = k0 + k;
                int t = kk >> 9, c = kk & 511;
                int l = l0 + n + t - 4;
                bf16 vh = __float2bfloat16(0.f), vl = vh;
                if (l >= 0) {
                    size_t gb = (size_t)c * L_ + l;
                    vh = Bgh[gb]; vl = Bgl[gb];
                }
                Bs_h[n * APAD + k] = vh;
                Bs_l[n * APAD + k] = vl;
            }
        } else {
#pragma unroll
            for (int i = 0; i < 8; i++) {
                int u = i * 256 + tid;
                int k = u >> 6, np = u & 63;
                size_t gb = (size_t)(k0 + k) * L_ + l0 + (np << 1);
                __nv_bfloat162 vh = *(const __nv_bfloat162*)&Bgh[gb];
                __nv_bfloat162 vl = *(const __nv_bfloat162*)&Bgl[gb];
                Bs_h[(np * 2) * APAD + k]     = vh.x;
                Bs_h[(np * 2 + 1) * APAD + k] = vh.y;
                Bs_l[(np * 2) * APAD + k]     = vl.x;
                Bs_l[(np * 2 + 1) * APAD + k] = vl.y;
            }
        }
        __syncthreads();

#pragma unroll
        for (int ks = 0; ks < BK; ks += 16) {
            const int kb = ks + (lane & 3) * 2;
            unsigned ah[2][4], al[2][4];
#pragma unroll
            for (int mt = 0; mt < 2; mt++) {
                int rb = wm * 32 + mt * 16 + (lane >> 2);
                ah[mt][0] = *(unsigned*)&As_h[rb * APAD + kb];
                ah[mt][1] = *(unsigned*)&As_h[(rb + 8) * APAD + kb];
                ah[mt][2] = *(unsigned*)&As_h[rb * APAD + kb + 8];
                ah[mt][3] = *(unsigned*)&As_h[(rb + 8) * APAD + kb + 8];
                al[mt][0] = *(unsigned*)&As_l[rb * APAD + kb];
                al[mt][1] = *(unsigned*)&As_l[(rb + 8) * APAD + kb];
                al[mt][2] = *(unsigned*)&As_l[rb * APAD + kb + 8];
                al[mt][3] = *(unsigned*)&As_l[(rb + 8) * APAD + kb + 8];
            }
#pragma unroll
            for (int nt = 0; nt < 8; nt++) {
                int col = wn * 64 + nt * 8 + (lane >> 2);
                unsigned bh0 = *(unsigned*)&Bs_h[col * APAD + kb];
                unsigned bh1 = *(unsigned*)&Bs_h[col * APAD + kb + 8];
                unsigned bl0 = *(unsigned*)&Bs_l[col * APAD + kb];
                unsigned bl1 = *(unsigned*)&Bs_l[col * APAD + kb + 8];
#pragma unroll
                for (int mt = 0; mt < 2; mt++) {
                    mma_bf16(acc[mt][nt], ah[mt], bh0, bh1);
                    mma_bf16(acc[mt][nt], ah[mt], bl0, bl1);
                    mma_bf16(acc[mt][nt], al[mt], bh0, bh1);
                }
            }
        }
        __syncthreads();
    }

    // ---- epilogue: two 64-col passes through Cs[128][65] ----
#pragma unroll 1
    for (int p = 0; p < 2; p++) {
        if (wn == p) {
#pragma unroll
            for (int mt = 0; mt < 2; mt++)
#pragma unroll
                for (int nt = 0; nt < 8; nt++) {
                    int r = wm * 32 + mt * 16 + (lane >> 2);
                    int cl = nt * 8 + (lane & 3) * 2;
                    Cs[r * 65 + cl]           = acc[mt][nt][0];
                    Cs[r * 65 + cl + 1]       = acc[mt][nt][1];
                    Cs[(r + 8) * 65 + cl]     = acc[mt][nt][2];
                    Cs[(r + 8) * 65 + cl + 1] = acc[mt][nt][3];
                }
        }
        __syncthreads();
        const int lbase = l0 + p * 64;
        if (MODE == 0) {
            int ch0 = m0 >> 1;
#pragma unroll
            for (int i = 0; i < 16; i++) {
                int e = i * 256 + tid;
                int chl = e >> 6, ll = e & 63;
                float av = Cs[(chl * 2) * 65 + ll] + __ldg(&bias[ch0 + chl]);
                float bv = Cs[(chl * 2 + 1) * 65 + ll] + __ldg(&bias[512 + ch0 + chl]);
                float hv = av / (1.f + expf(-bv));
                size_t off = ((size_t)b * 512 + ch0 + chl) * L_ + lbase + ll;
                g_h[off] = hv;
                bf16 hi, lo; split2(hv, hi, lo);
                g_hh[off] = hi; g_hl[off] = lo;
            }
        } else if (MODE == 1) {
            // pass A (a fastest, coalesced we reads): Cs += b1 + we
#pragma unroll
            for (int i = 0; i < 32; i++) {
                int e = i * 256 + tid;
                int a = e & 127, ll = e >> 7;
                Cs[a * 65 + ll] += __ldg(&bias[m0 + a]) +
                    e1[((size_t)b * L_ + lbase + ll) * 512 + m0 + a];
            }
            __syncthreads();
            // pass B: write q split bf16, layout (b, l, a), coalesced over a
#pragma unroll
            for (int i = 0; i < 32; i++) {
                int e = i * 256 + tid;
                int a = e & 127, ll = e >> 7;
                float v = Cs[a * 65 + ll];
                bf16 hi, lo; split2(v, hi, lo);
                size_t off = ((size_t)b * L_ + lbase + ll) * 512 + m0 + a;
                g_qh[off] = hi; g_ql[off] = lo;
            }
        } else {
#pragma unroll
            for (int i = 0; i < 32; i++) {
                int e = i * 256 + tid;
                int cl_ = e >> 6, ll = e & 63;
                size_t off = ((size_t)b * 512 + m0 + cl_) * L_ + lbase + ll;
                outp[off] = Cs[cl_ * 65 + ll] + __ldg(&bias[m0 + cl_])
                          + g_h[off] + e1[off];
            }
        }
        __syncthreads();
    }
}

// ---------------------------------------------------------------------------
// Tensor-core attention. One block per (b, 128-l tile). 256 threads.
//  Phase S: score = Q·feat^T  (M=128 l, N=224 p, K=512 a), bf16-split x3
//  Softmax over p (196 valid), writes attn output + probs to smem (pad=0)
//  Phase C: ctx = attn·feat   (M=128 l, N=512 a, K=224 p), A split on the fly
// Dynamic smem (bytes):
//  [0, 116736)        ss fp32 [128][228]
//  [116736, 173056)   phase-S tiles (As/Bs hi+lo, pitch 40)  |  phase-C Cs [128][65] fp32
//  [173056, 231424)   phase-C Bc hi+lo [64][228]
// ---------------------------------------------------------------------------
#define SSP 228
#define ATTN_SMEM_BYTES 231424

__global__ __launch_bounds__(256, 1) void attn_tc_kernel(float* __restrict__ attn_out) {
    extern __shared__ __align__(16) unsigned char dynsm[];
    float* ss  = (float*)dynsm;                    // [128][SSP]
    bf16* As_h = (bf16*)(dynsm + 116736);
    bf16* As_l = As_h + 128 * APAD;
    bf16* Bs_h = As_l + 128 * APAD;
    bf16* Bs_l = Bs_h + PP * APAD;
    float* Cs  = (float*)(dynsm + 116736);         // alias tiles region
    bf16* Bc_h = (bf16*)(dynsm + 173056);
    bf16* Bc_l = Bc_h + 64 * SSP;

    const int b  = blockIdx.y;
    const int l0 = blockIdx.x * 128;
    const int tid = threadIdx.x;
    const int lane = tid & 31, warp = tid >> 5;
    const int wm = warp >> 1, wn = warp & 1;

    // ================= Phase S: score GEMM =================
    float acc[2][14][4];
#pragma unroll
    for (int mt = 0; mt < 2; mt++)
#pragma unroll
        for (int nt = 0; nt < 14; nt++)
#pragma unroll
            for (int j = 0; j < 4; j++) acc[mt][nt][j] = 0.f;

    for (int k0 = 0; k0 < 512; k0 += BK) {
        // A: Q tile [128][32] from (b, l, a)
#pragma unroll
        for (int i = 0; i < 8; i++) {
            int u = i * 256 + tid;
            int row = u >> 4, kp = (u & 15) << 1;
            size_t ga = ((size_t)b * L_ + l0 + row) * 512 + k0 + kp;
            *(unsigned*)&As_h[row * APAD + kp] = *(const unsigned*)&g_qh[ga];
            *(unsigned*)&As_l[row * APAD + kp] = *(const unsigned*)&g_ql[ga];
        }
        // B: feat^T tile [224][32] from (b, p, a)
#pragma unroll
        for (int i = 0; i < 14; i++) {
            int u = i * 256 + tid;
            int row = u >> 4, kp = (u & 15) << 1;
            size_t gb = ((size_t)b * PP + row) * 512 + k0 + kp;
            *(unsigned*)&Bs_h[row * APAD + kp] = *(const unsigned*)&g_fTh[gb];
            *(unsigned*)&Bs_l[row * APAD + kp] = *(const unsigned*)&g_fTl[gb];
        }
        __syncthreads();

#pragma unroll
        for (int ks = 0; ks < BK; ks += 16) {
            const int kb = ks + (lane & 3) * 2;
            unsigned ah[2][4], al[2][4];
#pragma unroll
            for (int mt = 0; mt < 2; mt++) {
                int rb = wm * 32 + mt * 16 + (lane >> 2);
                ah[mt][0] = *(unsigned*)&As_h[rb * APAD + kb];
                ah[mt][1] = *(unsigned*)&As_h[(rb + 8) * APAD + kb];
                ah[mt][2] = *(unsigned*)&As_h[rb * APAD + kb + 8];
                ah[mt][3] = *(unsigned*)&As_h[(rb + 8) * APAD + kb + 8];
                al[mt][0] = *(unsigned*)&As_l[rb * APAD + kb];
                al[mt][1] = *(unsigned*)&As_l[(rb + 8) * APAD + kb];
                al[mt][2] = *(unsigned*)&As_l[rb * APAD + kb + 8];
                al[mt][3] = *(unsigned*)&As_l[(rb + 8) * APAD + kb + 8];
            }
#pragma unroll
            for (int nt = 0; nt < 14; nt++) {
                int col = wn * 112 + nt * 8 + (lane >> 2);
                unsigned bh0 = *(unsigned*)&Bs_h[col * APAD + kb];
                unsigned bh1 = *(unsigned*)&Bs_h[col * APAD + kb + 8];
                unsigned bl0 = *(unsigned*)&Bs_l[col * APAD + kb];
                unsigned bl1 = *(unsigned*)&Bs_l[col * APAD + kb + 8];
#pragma unroll
                for (int mt = 0; mt < 2; mt++) {
                    mma_bf16(acc[mt][nt], ah[mt], bh0, bh1);
                    mma_bf16(acc[mt][nt], ah[mt], bl0, bl1);
                    mma_bf16(acc[mt][nt], al[mt], bh0, bh1);
                }
            }
        }
        __syncthreads();
    }

    // scatter scores to ss
#pragma unroll
    for (int mt = 0; mt < 2; mt++)
#pragma unroll
        for (int nt = 0; nt < 14; nt++) {
            int r = wm * 32 + mt * 16 + (lane >> 2);
            int cl = wn * 112 + nt * 8 + (lane & 3) * 2;
            ss[r * SSP + cl]           = acc[mt][nt][0];
            ss[r * SSP + cl + 1]       = acc[mt][nt][1];
            ss[(r + 8) * SSP + cl]     = acc[mt][nt][2];
            ss[(r + 8) * SSP + cl + 1] = acc[mt][nt][3];
        }
    __syncthreads();

    // ================= Softmax (8 warps x 16 rows) =================
    for (int r = 0; r < 16; r++) {
        int row = warp * 16 + r;
        float v[7];
        float mx = -1e30f;
#pragma unroll
        for (int k = 0; k < 7; k++) {
            int p = lane + 32 * k;
            v[k] = (p < HW) ? ss[row * SSP + p] : -1e30f;
            mx = fmaxf(mx, v[k]);
        }
#pragma unroll
        for (int off = 16; off > 0; off >>= 1)
            mx = fmaxf(mx, __shfl_xor_sync(0xffffffffu, mx, off));
        float s = 0.f;
#pragma unroll
        for (int k = 0; k < 7; k++) {
            int p = lane + 32 * k;
            if (p < HW) { v[k] = expf(v[k] - mx); s += v[k]; }
        }
#pragma unroll
        for (int off = 16; off > 0; off >>= 1)
            s += __shfl_xor_sync(0xffffffffu, s, off);
        float inv = 1.f / s;
        float* ao = attn_out + ((size_t)b * L_ + l0 + row) * HW;
#pragma unroll
        for (int k = 0; k < 7; k++) {
            int p = lane + 32 * k;
            if (p < HW) {
                float a = v[k] * inv;
                ss[row * SSP + p] = a;
                ao[p] = a;
            } else {
                ss[row * SSP + p] = 0.f;
            }
        }
    }
    __syncthreads();

    // ================= Phase C: ctx GEMM =================
#pragma unroll 1
    for (int a0 = 0; a0 < 512; a0 += 64) {
        // stage Bc [64 a][224 p] hi/lo from (b, a, PP)
#pragma unroll
        for (int i = 0; i < 28; i++) {
            int u = i * 256 + tid;
            int row = u / 112, pc = (u - row * 112) * 2;
            size_t gb = ((size_t)b * 512 + a0 + row) * PP + pc;
            *(unsigned*)&Bc_h[row * SSP + pc] = *(const unsigned*)&g_fh[gb];
            *(unsigned*)&Bc_l[row * SSP + pc] = *(const unsigned*)&g_fl[gb];
        }
        __syncthreads();

        float ac2[2][4][4];
#pragma unroll
        for (int mt = 0; mt < 2; mt++)
#pragma unroll
            for (int nt = 0; nt < 4; nt++)
#pragma unroll
                for (int j = 0; j < 4; j++) ac2[mt][nt][j] = 0.f;

#pragma unroll 2
        for (int p0 = 0; p0 < PP; p0 += 16) {
            const int kb = p0 + (lane & 3) * 2;
            unsigned ah[2][4], al[2][4];
#pragma unroll
            for (int mt = 0; mt < 2; mt++) {
                int rb = wm * 32 + mt * 16 + (lane >> 2);
#pragma unroll
                for (int f = 0; f < 4; f++) {
                    int rr = rb + ((f & 1) ? 8 : 0);
                    int cc = kb + ((f & 2) ? 8 : 0);
                    float2 v = *(const float2*)&ss[rr * SSP + cc];
                    bf16 h0 = __float2bfloat16(v.x);
                    bf16 h1 = __float2bfloat16(v.y);
                    __nv_bfloat162 hp; hp.x = h0; hp.y = h1;
                    __nv_bfloat162 lp;
                    lp.x = __float2bfloat16(v.x - __bfloat162float(h0));
                    lp.y = __float2bfloat16(v.y - __bfloat162float(h1));
                    ah[mt][f] = *(unsigned*)&hp;
                    al[mt][f] = *(unsigned*)&lp;
                }
            }
#pragma unroll
            for (int nt = 0; nt < 4; nt++) {
                int col = wn * 32 + nt * 8 + (lane >> 2);
                unsigned bh0 = *(unsigned*)&Bc_h[col * SSP + kb];
                unsigned bh1 = *(unsigned*)&Bc_h[col * SSP + kb + 8];
                unsigned bl0 = *(unsigned*)&Bc_l[col * SSP + kb];
                unsigned bl1 = *(unsigned*)&Bc_l[col * SSP + kb + 8];
#pragma unroll
                for (int mt = 0; mt < 2; mt++) {
                    mma_bf16(ac2[mt][nt], ah[mt], bh0, bh1);
                    mma_bf16(ac2[mt][nt], ah[mt], bl0, bl1);
                    mma_bf16(ac2[mt][nt], al[mt], bh0, bh1);
                }
            }
        }

        // stage to Cs [128 l][64 a, pitch 65]
#pragma unroll
        for (int mt = 0; mt < 2; mt++)
#pragma unroll
            for (int nt = 0; nt < 4; nt++) {
                int r = wm * 32 + mt * 16 + (lane >> 2);
                int cl = wn * 32 + nt * 8 + (lane & 3) * 2;
                Cs[r * 65 + cl]           = ac2[mt][nt][0];
                Cs[r * 65 + cl + 1]       = ac2[mt][nt][1];
                Cs[(r + 8) * 65 + cl]     = ac2[mt][nt][2];
                Cs[(r + 8) * 65 + cl + 1] = ac2[mt][nt][3];
            }
        __syncthreads();

        // write ctx split bf16, layout (b, a, l), coalesced over l
#pragma unroll
        for (int i = 0; i < 32; i++) {
            int e = i * 256 + tid;
            int a = e >> 7, l = e & 127;
            float v = Cs[l * 65 + a];
            bf16 hi, lo; split2(v, hi, lo);
            size_t off = ((size_t)b * 512 + a0 + a) * L_ + l0 + l;
            g_cxh[off] = hi; g_cxl[off] = lo;
        }
        __syncthreads();
    }
}

// ---------------------------------------------------------------------------
extern "C" void kernel_launch(void* const* d_in, const int* in_sizes, int n_in,
                              void* d_out, int out_size) {
    (void)in_sizes; (void)n_in; (void)out_size;
    const float* x      = (const float*)d_in[0];
    const float* we     = (const float*)d_in[1];
    const float* img    = (const float*)d_in[2];
    /* d_in[3] prev_attn unused */
    const float* conv_v = (const float*)d_in[4];
    const float* conv_g = (const float*)d_in[5];
    const float* conv_b = (const float*)d_in[6];
    const float* fc1_w  = (const float*)d_in[7];
    const float* fc1_b  = (const float*)d_in[8];
    const float* fc2_w  = (const float*)d_in[9];
    const float* fc2_b  = (const float*)d_in[10];
    float* out = (float*)d_out;

    // passthrough copies
    cudaMemcpyAsync(out + OUT_WE, we, (size_t)B_ * L_ * DW * sizeof(float),
                    cudaMemcpyDeviceToDevice, 0);
    cudaMemcpyAsync(out + OUT_IMG, img, (size_t)B_ * DW * HW * sizeof(float),
                    cudaMemcpyDeviceToDevice, 0);

    // device-symbol addresses for split targets
    void *p_xh, *p_xl, *p_w1h, *p_w1l, *p_w2h, *p_w2l;
    cudaGetSymbolAddress(&p_xh, g_xh);
    cudaGetSymbolAddress(&p_xl, g_xl);
    cudaGetSymbolAddress(&p_w1h, g_w1h);
    cudaGetSymbolAddress(&p_w1l, g_w1l);
    cudaGetSymbolAddress(&p_w2h, g_w2h);
    cudaGetSymbolAddress(&p_w2l, g_w2l);

    // prep
    wnorm_kernel<<<COUT, 256>>>(conv_v, conv_g);
    convw_split_kernel<<<COUT, 256>>>();
    split_kernel<<<2048, 256>>>(x, (bf16*)p_xh, (bf16*)p_xl, B_ * CIN * L_);
    split_kernel<<<256, 256>>>(fc1_w, (bf16*)p_w1h, (bf16*)p_w1l, DW * DW);
    split_kernel<<<256, 256>>>(fc2_w, (bf16*)p_w2h, (bf16*)p_w2l, DW * DW);
    featT_kernel<<<dim3(PP / 32, 512 / 32, B_), dim3(32, 8)>>>(img);
    featpad_kernel<<<(B_ * 512 * PP + 255) / 256, 256>>>(img);

    // conv + GLU  (M=1024 interleaved, N=1024, K=2560)
    gemm_kernel<0><<<dim3(L_ / BN, COUT / BM, B_), 256>>>(conv_b, nullptr, nullptr);
    // fc1 (M=512, N=1024, K=512) -> q bf16 (b,l,a)
    gemm_kernel<1><<<dim3(L_ / BN, DW / BM, B_), 256>>>(fc1_b, we, nullptr);

    // tensor-core attention
    cudaFuncSetAttribute(attn_tc_kernel, cudaFuncAttributeMaxDynamicSharedMemorySize,
                         ATTN_SMEM_BYTES);
    attn_tc_kernel<<<dim3(L_ / 128, B_), 256, ATTN_SMEM_BYTES>>>(out + OUT_ATTN);

    // fc2 + residuals (M=512, N=1024, K=512)
    gemm_kernel<2><<<dim3(L_ / BN, DW / BM, B_), 256>>>(fc2_b, x, out);
}